// round 13
// baseline (speedup 1.0000x reference)
#include <cuda_runtime.h>
#include <stdint.h>
#include <math.h>

#define BSZ 2
#define SEQ 2048
#define EMB 768
#define NH  12
#define HD  64
#define BH  (BSZ*NH)     /* 24  */
#define MTOK (BSZ*SEQ)   /* 4096 */

// ---------------------------------------------------------------------------
// Scratch
// ---------------------------------------------------------------------------
__device__ float g_Q[BH * SEQ * HD];
__device__ float g_K[BH * SEQ * HD];
__device__ float g_V[BH * SEQ * HD];
__device__ float g_O[MTOK * EMB];          // attention out, tf32-rounded
__device__ float g_X[MTOK * EMB];          // tf32-rounded hidden states
__device__ float g_W4[4 * EMB * EMB];      // tf32-rounded Wq,Wk,Wv,Wo
__device__ int   g_mask_nz;

// ---------------------------------------------------------------------------
// Mask scan
// ---------------------------------------------------------------------------
__global__ void reset_flag_kernel() { g_mask_nz = 0; }

__global__ void scan_mask_kernel(const float* __restrict__ mask, int n4) {
    int i = blockIdx.x * blockDim.x + threadIdx.x;
    int stride = gridDim.x * blockDim.x;
    int nz = 0;
    for (; i < n4; i += stride) {
        float4 v = ((const float4*)mask)[i];
        nz |= (v.x != 0.f) | (v.y != 0.f) | (v.z != 0.f) | (v.w != 0.f);
    }
    if (__syncthreads_or(nz)) {
        if (threadIdx.x == 0) atomicOr(&g_mask_nz, 1);
    }
}

// ---------------------------------------------------------------------------
// tf32 / cp.async helpers
// ---------------------------------------------------------------------------
__device__ __forceinline__ unsigned cvt_tf32(float x) {
    unsigned r;
    asm("cvt.rna.tf32.f32 %0, %1;" : "=r"(r) : "f"(x));
    return r;
}
__device__ __forceinline__ float cvt_tf32_f(float x) {
    return __uint_as_float(cvt_tf32(x));
}

__device__ __forceinline__ void mma_tf32(float c[4], const unsigned a[4],
                                         unsigned b0, unsigned b1) {
    asm("mma.sync.aligned.m16n8k8.row.col.f32.tf32.tf32.f32 "
        "{%0,%1,%2,%3},{%4,%5,%6,%7},{%8,%9},{%0,%1,%2,%3};"
        : "+f"(c[0]), "+f"(c[1]), "+f"(c[2]), "+f"(c[3])
        : "r"(a[0]), "r"(a[1]), "r"(a[2]), "r"(a[3]), "r"(b0), "r"(b1));
}

__device__ __forceinline__ void cp_async16(unsigned saddr, const void* gptr) {
    asm volatile("cp.async.cg.shared.global [%0], [%1], 16;"
                 :: "r"(saddr), "l"(gptr));
}
__device__ __forceinline__ void cp_commit() {
    asm volatile("cp.async.commit_group;");
}
template <int N>
__device__ __forceinline__ void cp_wait() {
    asm volatile("cp.async.wait_group %0;" :: "n"(N));
}

// ---------------------------------------------------------------------------
// Pre-round pass: X and the 4 weight matrices -> tf32 (rna), into scratch.
// ---------------------------------------------------------------------------
__global__ void round_inputs_kernel(
    const float* __restrict__ X,
    const float* __restrict__ Wq, const float* __restrict__ Wk,
    const float* __restrict__ Wv, const float* __restrict__ Wo)
{
    int i = blockIdx.x * blockDim.x + threadIdx.x;
    int stride = gridDim.x * blockDim.x;
    const int NX = MTOK * EMB / 4;
    const int NW = EMB * EMB / 4;
    for (int k = i; k < NX; k += stride) {
        float4 v = ((const float4*)X)[k];
        v.x = cvt_tf32_f(v.x); v.y = cvt_tf32_f(v.y);
        v.z = cvt_tf32_f(v.z); v.w = cvt_tf32_f(v.w);
        ((float4*)g_X)[k] = v;
    }
    const float* Ws[4] = {Wq, Wk, Wv, Wo};
#pragma unroll
    for (int s = 0; s < 4; s++) {
        float4* dst = (float4*)(g_W4 + (size_t)s * EMB * EMB);
        const float4* src = (const float4*)Ws[s];
        for (int k = i; k < NW; k += stride) {
            float4 v = src[k];
            v.x = cvt_tf32_f(v.x); v.y = cvt_tf32_f(v.y);
            v.z = cvt_tf32_f(v.z); v.w = cvt_tf32_f(v.w);
            dst[k] = v;
        }
    }
}

// ---------------------------------------------------------------------------
// Pipelined tf32 GEMM core (R8 3-stage, one sync/iter) — best measured.
// ---------------------------------------------------------------------------
#define DSW 36
#define GST (128 * DSW)
#define NSTG 3
#define GEMM_SMEM (NSTG * 2 * GST * 4)

struct GemmAcc { float a[2][8][4]; };

__device__ __forceinline__ void gemm_pipe_core(
    const float* __restrict__ A, const float* __restrict__ W,
    int bm, int bn, GemmAcc& acc, float* sm)
{
    int tid = threadIdx.x;
    int lane = tid & 31;
    int wid = tid >> 5;
    int g = lane >> 2, m = lane & 3;
    int wm = wid & 3, wn = wid >> 2;

#pragma unroll
    for (int im = 0; im < 2; im++)
#pragma unroll
        for (int jn = 0; jn < 8; jn++)
#pragma unroll
            for (int i = 0; i < 4; i++) acc.a[im][jn][i] = 0.f;

    unsigned sbase = (unsigned)__cvta_generic_to_shared(sm);
    int rowc = tid >> 1;
    int cOff = (tid & 1) * 4;
    const float* agp = A + (size_t)(bm + rowc) * EMB + cOff * 4;
    const float* bgp = W + (size_t)(bn + rowc) * EMB + cOff * 4;
    unsigned soff = (unsigned)(rowc * DSW + cOff * 4) * 4;

    auto issue = [&](int it) {
        int st = it % NSTG;
        unsigned as = sbase + (unsigned)st * (2 * GST * 4);
        unsigned bs = as + GST * 4;
        int k0 = it * 32;
#pragma unroll
        for (int u = 0; u < 4; u++) {
            cp_async16(as + soff + u * 16, agp + k0 + u * 4);
            cp_async16(bs + soff + u * 16, bgp + k0 + u * 4);
        }
        cp_commit();
    };

    const int NIT = EMB / 32;
    issue(0);
    issue(1);

    for (int it = 0; it < NIT; it++) {
        if (it + 1 < NIT) cp_wait<1>();
        else              cp_wait<0>();
        __syncthreads();
        if (it + 2 < NIT) issue(it + 2);

        const float* As = sm + (it % NSTG) * 2 * GST;
        const float* Bs = As + GST;

#pragma unroll
        for (int t = 0; t < 4; t++) {
            unsigned af[2][4];
#pragma unroll
            for (int im = 0; im < 2; im++) {
                const float* ab = As + (wm * 32 + im * 16 + g) * DSW + 8 * t + m;
                af[im][0] = __float_as_uint(ab[0]);
                af[im][2] = __float_as_uint(ab[4]);
                af[im][1] = __float_as_uint(ab[8 * DSW]);
                af[im][3] = __float_as_uint(ab[8 * DSW + 4]);
            }
#pragma unroll
            for (int jn = 0; jn < 8; jn++) {
                const float* bb = Bs + (wn * 64 + jn * 8 + g) * DSW + 8 * t + m;
                unsigned b0 = __float_as_uint(bb[0]);
                unsigned b1 = __float_as_uint(bb[4]);
                mma_tf32(acc.a[0][jn], af[0], b0, b1);
                mma_tf32(acc.a[1][jn], af[1], b0, b1);
            }
        }
    }
}

// ---------------------------------------------------------------------------
// QKV projection: grid (18, 32). Writes [bh][s][d], tf32-rounded (Q scaled).
// ---------------------------------------------------------------------------
__global__ void __launch_bounds__(256) qkv_gemm_pipe_kernel(
    const float* __restrict__ bq, const float* __restrict__ bk,
    const float* __restrict__ bv)
{
    extern __shared__ __align__(16) float sm[];

    int bx  = blockIdx.x;
    int seg = bx / 6;
    int nb  = bx % 6;
    int bm  = blockIdx.y * 128;

    const float* W    = g_W4 + (size_t)seg * EMB * EMB;
    const float* bias = (seg == 0) ? bq : (seg == 1) ? bk : bv;
    float*       out  = (seg == 0) ? g_Q : (seg == 1) ? g_K : g_V;
    const float scale = (seg == 0) ? 0.125f : 1.0f;

    GemmAcc acc;
    gemm_pipe_core(g_X, W, bm, nb * 128, acc, sm);

    int lane = threadIdx.x & 31;
    int wid  = threadIdx.x >> 5;
    int g = lane >> 2, m = lane & 3;
    int wm = wid & 3, wn = wid >> 2;

#pragma unroll
    for (int im = 0; im < 2; im++) {
        int r0 = bm + wm * 32 + im * 16 + g;
#pragma unroll
        for (int jn = 0; jn < 8; jn++) {
            int nloc = nb * 128 + wn * 64 + jn * 8 + 2 * m;
            int h = nloc >> 6, d = nloc & 63;
            float b0v = bias[nloc], b1v = bias[nloc + 1];
            int b = r0 >> 11, s0 = r0 & 2047;
            float* o0 = out + ((size_t)((b * NH + h) * SEQ + s0)) * HD + d;
            float* o1 = o0 + (size_t)8 * HD;
            *(float2*)o0 = make_float2(cvt_tf32_f((acc.a[im][jn][0] + b0v) * scale),
                                       cvt_tf32_f((acc.a[im][jn][1] + b1v) * scale));
            *(float2*)o1 = make_float2(cvt_tf32_f((acc.a[im][jn][2] + b0v) * scale),
                                       cvt_tf32_f((acc.a[im][jn][3] + b1v) * scale));
        }
    }
}

// ---------------------------------------------------------------------------
// Output projection: grid (6, 32). d_out = g_O @ Wo^T + bo (fp32 out).
// ---------------------------------------------------------------------------
__global__ void __launch_bounds__(256) oproj_gemm_pipe_kernel(
    const float* __restrict__ bias, float* __restrict__ C)
{
    extern __shared__ __align__(16) float sm[];

    int bn = blockIdx.x * 128;
    int bm = blockIdx.y * 128;

    GemmAcc acc;
    gemm_pipe_core(g_O, g_W4 + (size_t)3 * EMB * EMB, bm, bn, acc, sm);

    int lane = threadIdx.x & 31;
    int wid  = threadIdx.x >> 5;
    int g = lane >> 2, m = lane & 3;
    int wm = wid & 3, wn = wid >> 2;

#pragma unroll
    for (int im = 0; im < 2; im++) {
        int r0 = bm + wm * 32 + im * 16 + g;
#pragma unroll
        for (int jn = 0; jn < 8; jn++) {
            int n = bn + wn * 64 + jn * 8 + 2 * m;
            float b0v = bias[n], b1v = bias[n + 1];
            float* o0 = C + (size_t)r0 * EMB + n;
            float* o1 = o0 + (size_t)8 * EMB;
            *(float2*)o0 = make_float2(acc.a[im][jn][0] + b0v, acc.a[im][jn][1] + b1v);
            *(float2*)o1 = make_float2(acc.a[im][jn][2] + b0v, acc.a[im][jn][3] + b1v);
        }
    }
}

// ---------------------------------------------------------------------------
// Flash attention v4: 256 threads / 8 warps, 16 q-rows per warp (im=1).
// Halved per-warp register state -> 2 CTAs x 8 warps = 16 warps/SM.
// Shuffle-free PV (key-slot permutation) retained. Same math order per
// q-row as v3 -> numerics identical.
// ---------------------------------------------------------------------------
#define KVS    68
#define TILE_F (64 * KVS)
#define ATT_SMEM (4 * TILE_F * 4)

__global__ void __launch_bounds__(256, 2) attn_tc3_kernel(
    const float* __restrict__ mask,
    const float* __restrict__ attn_bias,
    const float* __restrict__ beta_p,
    const float* __restrict__ bbias_p)
{
    extern __shared__ __align__(16) float sm[];

    int qt   = blockIdx.x;
    int bh   = blockIdx.y;
    int b    = bh / NH;
    int h    = bh % NH;
    int q0   = qt * 128;
    int tid  = threadIdx.x;
    int w    = tid >> 5;           // 0..7, warp owns q rows q0+w*16..+15
    int lane = tid & 31;
    int g    = lane >> 2;
    int m    = lane & 3;

    const float beta  = beta_p[0];
    const float bbias = bbias_p[0];
    const int masknz  = g_mask_nz;

    const float* Kg    = g_K + (size_t)bh * SEQ * HD;
    const float* Vg    = g_V + (size_t)bh * SEQ * HD;
    const float* biasg = attn_bias + (size_t)bh * SEQ;

    // Q fragments: 16 rows x 64 cols, pre-rounded tf32 in g_Q
    unsigned qf[8][4];
    {
        const float* r0 = g_Q + ((size_t)bh * SEQ + q0 + w * 16 + g) * HD;
        const float* r1 = r0 + 8 * HD;
#pragma unroll
        for (int t = 0; t < 8; t++) {
            qf[t][0] = __float_as_uint(r0[8 * t + m]);
            qf[t][1] = __float_as_uint(r1[8 * t + m]);
            qf[t][2] = __float_as_uint(r0[8 * t + m + 4]);
            qf[t][3] = __float_as_uint(r1[8 * t + m + 4]);
        }
    }

    float mr0 = -1e30f, mr1 = -1e30f;
    float lr0 = 0.f,    lr1 = 0.f;
    float oa[8][4];
#pragma unroll
    for (int d = 0; d < 8; d++)
#pragma unroll
        for (int i = 0; i < 4; i++) oa[d][i] = 0.f;

    unsigned sbase = (unsigned)__cvta_generic_to_shared(sm);
    int lrow = tid >> 2;     // 0..63 (4 threads per row)
    int cir  = tid & 3;      // chunk group

    auto issue_tile = [&](int kt) {
        unsigned kst = sbase + (unsigned)(kt & 1) * (2 * TILE_F * 4);
        unsigned vst = kst + TILE_F * 4;
        const float* kp = Kg + (size_t)(kt * 64 + lrow) * HD;
        const float* vp = Vg + (size_t)(kt * 64 + lrow) * HD;
#pragma unroll
        for (int u = 0; u < 4; u++) {
            int c4 = (cir + 4 * u) * 4;          // float column
            unsigned soff = (unsigned)(lrow * KVS + c4) * 4;
            cp_async16(kst + soff, kp + c4);
            cp_async16(vst + soff, vp + c4);
        }
        cp_commit();
    };

    issue_tile(0);

    const int NT = SEQ / 64;
    for (int kt = 0; kt < NT; kt++) {
        if (kt + 1 < NT) { issue_tile(kt + 1); cp_wait<1>(); }
        else             { cp_wait<0>(); }
        __syncthreads();

        const float* Ksb = sm + (kt & 1) * 2 * TILE_F;
        const float* Vsb = Ksb + TILE_F;
        int k0 = kt * 64;

        // ---- Scores ----
        float sc[8][4];
#pragma unroll
        for (int j = 0; j < 8; j++)
#pragma unroll
            for (int i = 0; i < 4; i++) sc[j][i] = 0.f;

#pragma unroll
        for (int t = 0; t < 8; t++) {
#pragma unroll
            for (int j = 0; j < 8; j++) {
                const float* kr = Ksb + (8 * j + g) * KVS + 8 * t + m;
                unsigned b0 = __float_as_uint(kr[0]);
                unsigned b1 = __float_as_uint(kr[4]);
                mma_tf32(sc[j], qf[t], b0, b1);
            }
        }

        // ---- bias (+mask) ----
#pragma unroll
        for (int j = 0; j < 8; j++) {
            float2 bv = *(const float2*)(biasg + k0 + 8 * j + 2 * m);
            float b0v = beta * bv.x + bbias;
            float b1v = beta * bv.y + bbias;
            sc[j][0] += b0v; sc[j][1] += b1v;
            sc[j][2] += b0v; sc[j][3] += b1v;
            if (masknz) {
                int qr = q0 + w * 16 + g;
                const float* m0p = mask + ((size_t)b * SEQ + qr) * SEQ + k0 + 8 * j + 2 * m;
                const float* m1p = m0p + (size_t)8 * SEQ;
                sc[j][0] += m0p[0]; sc[j][1] += m0p[1];
                sc[j][2] += m1p[0]; sc[j][3] += m1p[1];
            }
        }

        // ---- Online softmax ----
        float mx0 = sc[0][0], mx1 = sc[0][2];
#pragma unroll
        for (int j = 0; j < 8; j++) {
            mx0 = fmaxf(mx0, fmaxf(sc[j][0], sc[j][1]));
            mx1 = fmaxf(mx1, fmaxf(sc[j][2], sc[j][3]));
        }
        mx0 = fmaxf(mx0, __shfl_xor_sync(0xffffffffu, mx0, 1));
        mx0 = fmaxf(mx0, __shfl_xor_sync(0xffffffffu, mx0, 2));
        mx1 = fmaxf(mx1, __shfl_xor_sync(0xffffffffu, mx1, 1));
        mx1 = fmaxf(mx1, __shfl_xor_sync(0xffffffffu, mx1, 2));

        float mn0 = fmaxf(mr0, mx0);
        float mn1 = fmaxf(mr1, mx1);
        float al0 = __expf(mr0 - mn0);
        float al1 = __expf(mr1 - mn1);

        float s0 = 0.f, s1 = 0.f;
#pragma unroll
        for (int j = 0; j < 8; j++) {
            sc[j][0] = __expf(sc[j][0] - mn0);
            sc[j][1] = __expf(sc[j][1] - mn0);
            sc[j][2] = __expf(sc[j][2] - mn1);
            sc[j][3] = __expf(sc[j][3] - mn1);
            s0 += sc[j][0] + sc[j][1];
            s1 += sc[j][2] + sc[j][3];
        }
        s0 += __shfl_xor_sync(0xffffffffu, s0, 1);
        s0 += __shfl_xor_sync(0xffffffffu, s0, 2);
        s1 += __shfl_xor_sync(0xffffffffu, s1, 1);
        s1 += __shfl_xor_sync(0xffffffffu, s1, 2);

        lr0 = lr0 * al0 + s0;
        lr1 = lr1 * al1 + s1;
        mr0 = mn0; mr1 = mn1;
#pragma unroll
        for (int d = 0; d < 8; d++) {
            oa[d][0] *= al0; oa[d][1] *= al0;
            oa[d][2] *= al1; oa[d][3] *= al1;
        }

        // ---- PV: shuffle-free (key-slot permutation) ----
#pragma unroll
        for (int j = 0; j < 8; j++) {
            unsigned pa[4];
            pa[0] = cvt_tf32(sc[j][0]);
            pa[1] = cvt_tf32(sc[j][2]);
            pa[2] = cvt_tf32(sc[j][1]);
            pa[3] = cvt_tf32(sc[j][3]);
            const float* vr = Vsb + (8 * j + 2 * m) * KVS + g;
#pragma unroll
            for (int d = 0; d < 8; d++) {
                unsigned b0 = __float_as_uint(vr[8 * d]);
                unsigned b1 = __float_as_uint(vr[KVS + 8 * d]);
                mma_tf32(oa[d], pa, b0, b1);
            }
        }
        __syncthreads();
    }

    // ---- Epilogue: tf32-rounded O ----
    float inv0 = 1.f / lr0;
    float inv1 = 1.f / lr1;
    int qr = q0 + w * 16 + g;
    float* O0 = g_O + ((size_t)(b * SEQ + qr)) * EMB + h * HD;
    float* O1 = O0 + (size_t)8 * EMB;
#pragma unroll
    for (int d = 0; d < 8; d++) {
        int c = 8 * d + 2 * m;
        *(float2*)(O0 + c) = make_float2(cvt_tf32_f(oa[d][0] * inv0),
                                         cvt_tf32_f(oa[d][1] * inv0));
        *(float2*)(O1 + c) = make_float2(cvt_tf32_f(oa[d][2] * inv1),
                                         cvt_tf32_f(oa[d][3] * inv1));
    }
}

// ---------------------------------------------------------------------------
// Launch
// ---------------------------------------------------------------------------
extern "C" void kernel_launch(void* const* d_in, const int* in_sizes, int n_in,
                              void* d_out, int out_size) {
    const float* X     = (const float*)d_in[0];
    const float* mask  = (const float*)d_in[1];
    const float* abias = (const float*)d_in[2];
    const float* Wq    = (const float*)d_in[3];
    const float* bq    = (const float*)d_in[4];
    const float* Wk    = (const float*)d_in[5];
    const float* bk    = (const float*)d_in[6];
    const float* Wv    = (const float*)d_in[7];
    const float* bv    = (const float*)d_in[8];
    const float* Wo    = (const float*)d_in[9];
    const float* bo    = (const float*)d_in[10];
    const float* beta  = (const float*)d_in[11];
    const float* bbias = (const float*)d_in[12];
    float* out = (float*)d_out;

    cudaFuncSetAttribute(attn_tc3_kernel,
                         cudaFuncAttributeMaxDynamicSharedMemorySize, ATT_SMEM);
    cudaFuncSetAttribute(qkv_gemm_pipe_kernel,
                         cudaFuncAttributeMaxDynamicSharedMemorySize, GEMM_SMEM);
    cudaFuncSetAttribute(oproj_gemm_pipe_kernel,
                         cudaFuncAttributeMaxDynamicSharedMemorySize, GEMM_SMEM);

    reset_flag_kernel<<<1, 32>>>();
    scan_mask_kernel<<<1024, 256>>>(mask, BSZ * SEQ * SEQ / 4);
    round_inputs_kernel<<<512, 256>>>(X, Wq, Wk, Wv, Wo);
    qkv_gemm_pipe_kernel<<<dim3(18, 32), 256, GEMM_SMEM>>>(bq, bk, bv);
    attn_tc3_kernel<<<dim3(SEQ / 128, BH), 256, ATT_SMEM>>>(mask, abias, beta, bbias);
    oproj_gemm_pipe_kernel<<<dim3(6, 32), 256, GEMM_SMEM>>>(bo, out);
}

// round 15
// speedup vs baseline: 1.1405x; 1.1405x over previous
#include <cuda_runtime.h>
#include <stdint.h>
#include <math.h>

#define BSZ 2
#define SEQ 2048
#define EMB 768
#define NH  12
#define HD  64
#define BH  (BSZ*NH)     /* 24  */
#define MTOK (BSZ*SEQ)   /* 4096 */
#define NQT  (SEQ/128)   /* 16 q-tiles */
#define NSLOT (BH*NQT)   /* 384 */

// ---------------------------------------------------------------------------
// Scratch
// ---------------------------------------------------------------------------
__device__ float g_Q[BH * SEQ * HD];
__device__ float g_K[BH * SEQ * HD];
__device__ float g_V[BH * SEQ * HD];
__device__ float g_O[MTOK * EMB];          // merged attention out, tf32-rounded
__device__ float g_X[MTOK * EMB];          // tf32-rounded hidden states
__device__ float g_W4[4 * EMB * EMB];      // tf32-rounded Wq,Wk,Wv,Wo
__device__ float g_PO[2 * NSLOT * 128 * 64];   // split-KV partial O (unnormalized)
__device__ float g_PML[2 * NSLOT * 128 * 2];   // split-KV partial (m, l)
__device__ int   g_mask_nz;

// ---------------------------------------------------------------------------
// Mask scan
// ---------------------------------------------------------------------------
__global__ void reset_flag_kernel() { g_mask_nz = 0; }

__global__ void scan_mask_kernel(const float* __restrict__ mask, int n4) {
    int i = blockIdx.x * blockDim.x + threadIdx.x;
    int stride = gridDim.x * blockDim.x;
    int nz = 0;
    for (; i < n4; i += stride) {
        float4 v = ((const float4*)mask)[i];
        nz |= (v.x != 0.f) | (v.y != 0.f) | (v.z != 0.f) | (v.w != 0.f);
    }
    if (__syncthreads_or(nz)) {
        if (threadIdx.x == 0) atomicOr(&g_mask_nz, 1);
    }
}

// ---------------------------------------------------------------------------
// tf32 / cp.async helpers
// ---------------------------------------------------------------------------
__device__ __forceinline__ unsigned cvt_tf32(float x) {
    unsigned r;
    asm("cvt.rna.tf32.f32 %0, %1;" : "=r"(r) : "f"(x));
    return r;
}
__device__ __forceinline__ float cvt_tf32_f(float x) {
    return __uint_as_float(cvt_tf32(x));
}

__device__ __forceinline__ void mma_tf32(float c[4], const unsigned a[4],
                                         unsigned b0, unsigned b1) {
    asm("mma.sync.aligned.m16n8k8.row.col.f32.tf32.tf32.f32 "
        "{%0,%1,%2,%3},{%4,%5,%6,%7},{%8,%9},{%0,%1,%2,%3};"
        : "+f"(c[0]), "+f"(c[1]), "+f"(c[2]), "+f"(c[3])
        : "r"(a[0]), "r"(a[1]), "r"(a[2]), "r"(a[3]), "r"(b0), "r"(b1));
}

__device__ __forceinline__ void cp_async16(unsigned saddr, const void* gptr) {
    asm volatile("cp.async.cg.shared.global [%0], [%1], 16;"
                 :: "r"(saddr), "l"(gptr));
}
__device__ __forceinline__ void cp_commit() {
    asm volatile("cp.async.commit_group;");
}
template <int N>
__device__ __forceinline__ void cp_wait() {
    asm volatile("cp.async.wait_group %0;" :: "n"(N));
}

// ---------------------------------------------------------------------------
// Pre-round pass
// ---------------------------------------------------------------------------
__global__ void round_inputs_kernel(
    const float* __restrict__ X,
    const float* __restrict__ Wq, const float* __restrict__ Wk,
    const float* __restrict__ Wv, const float* __restrict__ Wo)
{
    int i = blockIdx.x * blockDim.x + threadIdx.x;
    int stride = gridDim.x * blockDim.x;
    const int NX = MTOK * EMB / 4;
    const int NW = EMB * EMB / 4;
    for (int k = i; k < NX; k += stride) {
        float4 v = ((const float4*)X)[k];
        v.x = cvt_tf32_f(v.x); v.y = cvt_tf32_f(v.y);
        v.z = cvt_tf32_f(v.z); v.w = cvt_tf32_f(v.w);
        ((float4*)g_X)[k] = v;
    }
    const float* Ws[4] = {Wq, Wk, Wv, Wo};
#pragma unroll
    for (int s = 0; s < 4; s++) {
        float4* dst = (float4*)(g_W4 + (size_t)s * EMB * EMB);
        const float4* src = (const float4*)Ws[s];
        for (int k = i; k < NW; k += stride) {
            float4 v = src[k];
            v.x = cvt_tf32_f(v.x); v.y = cvt_tf32_f(v.y);
            v.z = cvt_tf32_f(v.z); v.w = cvt_tf32_f(v.w);
            dst[k] = v;
        }
    }
}

// ---------------------------------------------------------------------------
// Pipelined tf32 GEMM core (R8 3-stage, one sync/iter) — best measured.
// ---------------------------------------------------------------------------
#define DSW 36
#define GST (128 * DSW)
#define NSTG 3
#define GEMM_SMEM (NSTG * 2 * GST * 4)

struct GemmAcc { float a[2][8][4]; };

__device__ __forceinline__ void gemm_pipe_core(
    const float* __restrict__ A, const float* __restrict__ W,
    int bm, int bn, GemmAcc& acc, float* sm)
{
    int tid = threadIdx.x;
    int lane = tid & 31;
    int wid = tid >> 5;
    int g = lane >> 2, m = lane & 3;
    int wm = wid & 3, wn = wid >> 2;

#pragma unroll
    for (int im = 0; im < 2; im++)
#pragma unroll
        for (int jn = 0; jn < 8; jn++)
#pragma unroll
            for (int i = 0; i < 4; i++) acc.a[im][jn][i] = 0.f;

    unsigned sbase = (unsigned)__cvta_generic_to_shared(sm);
    int rowc = tid >> 1;
    int cOff = (tid & 1) * 4;
    const float* agp = A + (size_t)(bm + rowc) * EMB + cOff * 4;
    const float* bgp = W + (size_t)(bn + rowc) * EMB + cOff * 4;
    unsigned soff = (unsigned)(rowc * DSW + cOff * 4) * 4;

    auto issue = [&](int it) {
        int st = it % NSTG;
        unsigned as = sbase + (unsigned)st * (2 * GST * 4);
        unsigned bs = as + GST * 4;
        int k0 = it * 32;
#pragma unroll
        for (int u = 0; u < 4; u++) {
            cp_async16(as + soff + u * 16, agp + k0 + u * 4);
            cp_async16(bs + soff + u * 16, bgp + k0 + u * 4);
        }
        cp_commit();
    };

    const int NIT = EMB / 32;
    issue(0);
    issue(1);

    for (int it = 0; it < NIT; it++) {
        if (it + 1 < NIT) cp_wait<1>();
        else              cp_wait<0>();
        __syncthreads();
        if (it + 2 < NIT) issue(it + 2);

        const float* As = sm + (it % NSTG) * 2 * GST;
        const float* Bs = As + GST;

#pragma unroll
        for (int t = 0; t < 4; t++) {
            unsigned af[2][4];
#pragma unroll
            for (int im = 0; im < 2; im++) {
                const float* ab = As + (wm * 32 + im * 16 + g) * DSW + 8 * t + m;
                af[im][0] = __float_as_uint(ab[0]);
                af[im][2] = __float_as_uint(ab[4]);
                af[im][1] = __float_as_uint(ab[8 * DSW]);
                af[im][3] = __float_as_uint(ab[8 * DSW + 4]);
            }
#pragma unroll
            for (int jn = 0; jn < 8; jn++) {
                const float* bb = Bs + (wn * 64 + jn * 8 + g) * DSW + 8 * t + m;
                unsigned b0 = __float_as_uint(bb[0]);
                unsigned b1 = __float_as_uint(bb[4]);
                mma_tf32(acc.a[0][jn], af[0], b0, b1);
                mma_tf32(acc.a[1][jn], af[1], b0, b1);
            }
        }
    }
}

// ---------------------------------------------------------------------------
// QKV projection: grid (18, 32). Writes [bh][s][d], tf32-rounded (Q scaled).
// ---------------------------------------------------------------------------
__global__ void __launch_bounds__(256) qkv_gemm_pipe_kernel(
    const float* __restrict__ bq, const float* __restrict__ bk,
    const float* __restrict__ bv)
{
    extern __shared__ __align__(16) float sm[];

    int bx  = blockIdx.x;
    int seg = bx / 6;
    int nb  = bx % 6;
    int bm  = blockIdx.y * 128;

    const float* W    = g_W4 + (size_t)seg * EMB * EMB;
    const float* bias = (seg == 0) ? bq : (seg == 1) ? bk : bv;
    float*       out  = (seg == 0) ? g_Q : (seg == 1) ? g_K : g_V;
    const float scale = (seg == 0) ? 0.125f : 1.0f;

    GemmAcc acc;
    gemm_pipe_core(g_X, W, bm, nb * 128, acc, sm);

    int lane = threadIdx.x & 31;
    int wid  = threadIdx.x >> 5;
    int g = lane >> 2, m = lane & 3;
    int wm = wid & 3, wn = wid >> 2;

#pragma unroll
    for (int im = 0; im < 2; im++) {
        int r0 = bm + wm * 32 + im * 16 + g;
#pragma unroll
        for (int jn = 0; jn < 8; jn++) {
            int nloc = nb * 128 + wn * 64 + jn * 8 + 2 * m;
            int h = nloc >> 6, d = nloc & 63;
            float b0v = bias[nloc], b1v = bias[nloc + 1];
            int b = r0 >> 11, s0 = r0 & 2047;
            float* o0 = out + ((size_t)((b * NH + h) * SEQ + s0)) * HD + d;
            float* o1 = o0 + (size_t)8 * HD;
            *(float2*)o0 = make_float2(cvt_tf32_f((acc.a[im][jn][0] + b0v) * scale),
                                       cvt_tf32_f((acc.a[im][jn][1] + b1v) * scale));
            *(float2*)o1 = make_float2(cvt_tf32_f((acc.a[im][jn][2] + b0v) * scale),
                                       cvt_tf32_f((acc.a[im][jn][3] + b1v) * scale));
        }
    }
}

// ---------------------------------------------------------------------------
// Output projection: grid (6, 32). d_out = g_O @ Wo^T + bo (fp32 out).
// ---------------------------------------------------------------------------
__global__ void __launch_bounds__(256) oproj_gemm_pipe_kernel(
    const float* __restrict__ bias, float* __restrict__ C)
{
    extern __shared__ __align__(16) float sm[];

    int bn = blockIdx.x * 128;
    int bm = blockIdx.y * 128;

    GemmAcc acc;
    gemm_pipe_core(g_O, g_W4 + (size_t)3 * EMB * EMB, bm, bn, acc, sm);

    int lane = threadIdx.x & 31;
    int wid  = threadIdx.x >> 5;
    int g = lane >> 2, m = lane & 3;
    int wm = wid & 3, wn = wid >> 2;

#pragma unroll
    for (int im = 0; im < 2; im++) {
        int r0 = bm + wm * 32 + im * 16 + g;
#pragma unroll
        for (int jn = 0; jn < 8; jn++) {
            int n = bn + wn * 64 + jn * 8 + 2 * m;
            float b0v = bias[n], b1v = bias[n + 1];
            float* o0 = C + (size_t)r0 * EMB + n;
            float* o1 = o0 + (size_t)8 * EMB;
            *(float2*)o0 = make_float2(acc.a[im][jn][0] + b0v, acc.a[im][jn][1] + b1v);
            *(float2*)o1 = make_float2(acc.a[im][jn][2] + b0v, acc.a[im][jn][3] + b1v);
        }
    }
}

// ---------------------------------------------------------------------------
// Flash attention v5: R9's proven inner loop (im=2, shuffle-free PV) with
// SPLIT-KV: blockIdx.z = half, each CTA covers 1024 keys for 128 q-rows.
// Grid (16, 24, 2) = 768 CTAs of half duration -> better wave packing.
// Partials (unnormalized O, per-row m and l) go to g_PO/g_PML; a merge
// kernel combines halves and writes tf32-rounded g_O.
// ---------------------------------------------------------------------------
#define KVS    68
#define TILE_F (64 * KVS)
#define ATT_SMEM (4 * TILE_F * 4)

__global__ void __launch_bounds__(128) attn_split_kernel(
    const float* __restrict__ mask,
    const float* __restrict__ attn_bias,
    const float* __restrict__ beta_p,
    const float* __restrict__ bbias_p)
{
    extern __shared__ __align__(16) float sm[];

    int qt   = blockIdx.x;
    int bh   = blockIdx.y;
    int half = blockIdx.z;
    int b    = bh / NH;
    int q0   = qt * 128;
    int tid  = threadIdx.x;
    int w    = tid >> 5;
    int lane = tid & 31;
    int g    = lane >> 2;
    int m    = lane & 3;

    const float beta  = beta_p[0];
    const float bbias = bbias_p[0];
    const int masknz  = g_mask_nz;

    const float* Kg    = g_K + (size_t)bh * SEQ * HD;
    const float* Vg    = g_V + (size_t)bh * SEQ * HD;
    const float* biasg = attn_bias + (size_t)bh * SEQ;

    unsigned qf[2][8][4];
    {
        const float* Qb = g_Q + ((size_t)bh * SEQ + q0 + w * 32) * HD;
#pragma unroll
        for (int im = 0; im < 2; im++) {
            const float* r0 = Qb + (size_t)(im * 16 + g) * HD;
            const float* r1 = r0 + 8 * HD;
#pragma unroll
            for (int t = 0; t < 8; t++) {
                qf[im][t][0] = __float_as_uint(r0[8 * t + m]);
                qf[im][t][1] = __float_as_uint(r1[8 * t + m]);
                qf[im][t][2] = __float_as_uint(r0[8 * t + m + 4]);
                qf[im][t][3] = __float_as_uint(r1[8 * t + m + 4]);
            }
        }
    }

    float mr[2][2], lrn[2][2];
    float oa[2][8][4];
#pragma unroll
    for (int im = 0; im < 2; im++) {
        mr[im][0] = -1e30f; mr[im][1] = -1e30f;
        lrn[im][0] = 0.f;   lrn[im][1] = 0.f;
#pragma unroll
        for (int d = 0; d < 8; d++)
#pragma unroll
            for (int i = 0; i < 4; i++) oa[im][d][i] = 0.f;
    }

    unsigned sbase = (unsigned)__cvta_generic_to_shared(sm);
    int lrow = tid >> 4;
    int cir  = tid & 15;

    const int HT = SEQ / 128;          // 16 tiles per half
    int kt0 = half * HT;

    auto issue_tile = [&](int lt) {    // lt = local tile idx 0..HT-1
        unsigned kst = sbase + (unsigned)(lt & 1) * (2 * TILE_F * 4);
        unsigned vst = kst + TILE_F * 4;
        const float* kp = Kg + (size_t)((kt0 + lt) * 64) * HD;
        const float* vp = Vg + (size_t)((kt0 + lt) * 64) * HD;
#pragma unroll
        for (int u = 0; u < 8; u++) {
            int row = u * 8 + lrow;
            unsigned soff = (unsigned)(row * KVS + cir * 4) * 4;
            cp_async16(kst + soff, kp + (size_t)row * HD + cir * 4);
            cp_async16(vst + soff, vp + (size_t)row * HD + cir * 4);
        }
        cp_commit();
    };

    issue_tile(0);

    for (int lt = 0; lt < HT; lt++) {
        if (lt + 1 < HT) { issue_tile(lt + 1); cp_wait<1>(); }
        else             { cp_wait<0>(); }
        __syncthreads();

        const float* Ksb = sm + (lt & 1) * 2 * TILE_F;
        const float* Vsb = Ksb + TILE_F;
        int k0 = (kt0 + lt) * 64;

        float sc[2][8][4];
#pragma unroll
        for (int im = 0; im < 2; im++)
#pragma unroll
            for (int j = 0; j < 8; j++)
#pragma unroll
                for (int i = 0; i < 4; i++) sc[im][j][i] = 0.f;

#pragma unroll
        for (int t = 0; t < 8; t++) {
#pragma unroll
            for (int j = 0; j < 8; j++) {
                const float* kr = Ksb + (8 * j + g) * KVS + 8 * t + m;
                unsigned b0 = __float_as_uint(kr[0]);
                unsigned b1 = __float_as_uint(kr[4]);
                mma_tf32(sc[0][j], qf[0][t], b0, b1);
                mma_tf32(sc[1][j], qf[1][t], b0, b1);
            }
        }

#pragma unroll
        for (int j = 0; j < 8; j++) {
            float2 bv = *(const float2*)(biasg + k0 + 8 * j + 2 * m);
            float b0v = beta * bv.x + bbias;
            float b1v = beta * bv.y + bbias;
#pragma unroll
            for (int im = 0; im < 2; im++) {
                sc[im][j][0] += b0v; sc[im][j][1] += b1v;
                sc[im][j][2] += b0v; sc[im][j][3] += b1v;
                if (masknz) {
                    int qr = q0 + w * 32 + im * 16 + g;
                    const float* m0p = mask + ((size_t)b * SEQ + qr) * SEQ + k0 + 8 * j + 2 * m;
                    const float* m1p = m0p + (size_t)8 * SEQ;
                    sc[im][j][0] += m0p[0]; sc[im][j][1] += m0p[1];
                    sc[im][j][2] += m1p[0]; sc[im][j][3] += m1p[1];
                }
            }
        }

#pragma unroll
        for (int im = 0; im < 2; im++) {
            float mx0 = sc[im][0][0], mx1 = sc[im][0][2];
#pragma unroll
            for (int j = 0; j < 8; j++) {
                mx0 = fmaxf(mx0, fmaxf(sc[im][j][0], sc[im][j][1]));
                mx1 = fmaxf(mx1, fmaxf(sc[im][j][2], sc[im][j][3]));
            }
            mx0 = fmaxf(mx0, __shfl_xor_sync(0xffffffffu, mx0, 1));
            mx0 = fmaxf(mx0, __shfl_xor_sync(0xffffffffu, mx0, 2));
            mx1 = fmaxf(mx1, __shfl_xor_sync(0xffffffffu, mx1, 1));
            mx1 = fmaxf(mx1, __shfl_xor_sync(0xffffffffu, mx1, 2));

            float mn0 = fmaxf(mr[im][0], mx0);
            float mn1 = fmaxf(mr[im][1], mx1);
            float al0 = __expf(mr[im][0] - mn0);
            float al1 = __expf(mr[im][1] - mn1);

            float s0 = 0.f, s1 = 0.f;
#pragma unroll
            for (int j = 0; j < 8; j++) {
                sc[im][j][0] = __expf(sc[im][j][0] - mn0);
                sc[im][j][1] = __expf(sc[im][j][1] - mn0);
                sc[im][j][2] = __expf(sc[im][j][2] - mn1);
                sc[im][j][3] = __expf(sc[im][j][3] - mn1);
                s0 += sc[im][j][0] + sc[im][j][1];
                s1 += sc[im][j][2] + sc[im][j][3];
            }
            s0 += __shfl_xor_sync(0xffffffffu, s0, 1);
            s0 += __shfl_xor_sync(0xffffffffu, s0, 2);
            s1 += __shfl_xor_sync(0xffffffffu, s1, 1);
            s1 += __shfl_xor_sync(0xffffffffu, s1, 2);

            lrn[im][0] = lrn[im][0] * al0 + s0;
            lrn[im][1] = lrn[im][1] * al1 + s1;
            mr[im][0] = mn0; mr[im][1] = mn1;
#pragma unroll
            for (int d = 0; d < 8; d++) {
                oa[im][d][0] *= al0; oa[im][d][1] *= al0;
                oa[im][d][2] *= al1; oa[im][d][3] *= al1;
            }
        }

#pragma unroll
        for (int j = 0; j < 8; j++) {
            unsigned pa[2][4];
#pragma unroll
            for (int im = 0; im < 2; im++) {
                pa[im][0] = cvt_tf32(sc[im][j][0]);
                pa[im][1] = cvt_tf32(sc[im][j][2]);
                pa[im][2] = cvt_tf32(sc[im][j][1]);
                pa[im][3] = cvt_tf32(sc[im][j][3]);
            }
            const float* vr = Vsb + (8 * j + 2 * m) * KVS + g;
#pragma unroll
            for (int d = 0; d < 8; d++) {
                unsigned b0 = __float_as_uint(vr[8 * d]);
                unsigned b1 = __float_as_uint(vr[KVS + 8 * d]);
                mma_tf32(oa[0][d], pa[0], b0, b1);
                mma_tf32(oa[1][d], pa[1], b0, b1);
            }
        }
        __syncthreads();
    }

    // ---- Partial epilogue: unnormalized O + (m, l) per row ----
    int slot = bh * NQT + qt;
    float* po = g_PO + ((size_t)(half * NSLOT + slot)) * 128 * 64;
    float* pml = g_PML + ((size_t)(half * NSLOT + slot)) * 128 * 2;
#pragma unroll
    for (int im = 0; im < 2; im++) {
        int r0 = w * 32 + im * 16 + g;       // local row, and r0+8
#pragma unroll
        for (int d = 0; d < 8; d++) {
            int c = 8 * d + 2 * m;
            *(float2*)(po + (size_t)r0 * 64 + c) =
                make_float2(oa[im][d][0], oa[im][d][1]);
            *(float2*)(po + (size_t)(r0 + 8) * 64 + c) =
                make_float2(oa[im][d][2], oa[im][d][3]);
        }
        if (m == 0) {
            pml[r0 * 2 + 0] = mr[im][0];
            pml[r0 * 2 + 1] = lrn[im][0];
            pml[(r0 + 8) * 2 + 0] = mr[im][1];
            pml[(r0 + 8) * 2 + 1] = lrn[im][1];
        }
    }
}

// ---------------------------------------------------------------------------
// Split-KV merge: combine the two halves' partial softmax, write g_O
// (tf32-rounded, [token][h*64+d] layout). Grid (384), 128 threads: one
// thread per row.
// ---------------------------------------------------------------------------
__global__ void __launch_bounds__(128) attn_merge_kernel()
{
    int slot = blockIdx.x;
    int r    = threadIdx.x;
    int bh   = slot / NQT;
    int qt   = slot % NQT;
    int b    = bh / NH;
    int h    = bh % NH;

    const float* pml0 = g_PML + ((size_t)slot) * 128 * 2 + r * 2;
    const float* pml1 = g_PML + ((size_t)(NSLOT + slot)) * 128 * 2 + r * 2;
    float m0 = pml0[0], l0 = pml0[1];
    float m1 = pml1[0], l1 = pml1[1];
    float M  = fmaxf(m0, m1);
    float a0 = __expf(m0 - M);
    float a1 = __expf(m1 - M);
    float inv = 1.f / (l0 * a0 + l1 * a1);
    a0 *= inv; a1 *= inv;

    const float4* o0 = (const float4*)(g_PO + ((size_t)slot) * 128 * 64 + (size_t)r * 64);
    const float4* o1 = (const float4*)(g_PO + ((size_t)(NSLOT + slot)) * 128 * 64 + (size_t)r * 64);
    int qr = qt * 128 + r;
    float* out = g_O + ((size_t)(b * SEQ + qr)) * EMB + h * HD;
#pragma unroll
    for (int c4 = 0; c4 < 16; c4++) {
        float4 v0 = o0[c4];
        float4 v1 = o1[c4];
        float4 v;
        v.x = cvt_tf32_f(v0.x * a0 + v1.x * a1);
        v.y = cvt_tf32_f(v0.y * a0 + v1.y * a1);
        v.z = cvt_tf32_f(v0.z * a0 + v1.z * a1);
        v.w = cvt_tf32_f(v0.w * a0 + v1.w * a1);
        ((float4*)out)[c4] = v;
    }
}

// ---------------------------------------------------------------------------
// Launch
// ---------------------------------------------------------------------------
extern "C" void kernel_launch(void* const* d_in, const int* in_sizes, int n_in,
                              void* d_out, int out_size) {
    const float* X     = (const float*)d_in[0];
    const float* mask  = (const float*)d_in[1];
    const float* abias = (const float*)d_in[2];
    const float* Wq    = (const float*)d_in[3];
    const float* bq    = (const float*)d_in[4];
    const float* Wk    = (const float*)d_in[5];
    const float* bk    = (const float*)d_in[6];
    const float* Wv    = (const float*)d_in[7];
    const float* bv    = (const float*)d_in[8];
    const float* Wo    = (const float*)d_in[9];
    const float* bo    = (const float*)d_in[10];
    const float* beta  = (const float*)d_in[11];
    const float* bbias = (const float*)d_in[12];
    float* out = (float*)d_out;

    cudaFuncSetAttribute(attn_split_kernel,
                         cudaFuncAttributeMaxDynamicSharedMemorySize, ATT_SMEM);
    cudaFuncSetAttribute(qkv_gemm_pipe_kernel,
                         cudaFuncAttributeMaxDynamicSharedMemorySize, GEMM_SMEM);
    cudaFuncSetAttribute(oproj_gemm_pipe_kernel,
                         cudaFuncAttributeMaxDynamicSharedMemorySize, GEMM_SMEM);

    reset_flag_kernel<<<1, 32>>>();
    scan_mask_kernel<<<1024, 256>>>(mask, BSZ * SEQ * SEQ / 4);
    round_inputs_kernel<<<512, 256>>>(X, Wq, Wk, Wv, Wo);
    qkv_gemm_pipe_kernel<<<dim3(18, 32), 256, GEMM_SMEM>>>(bq, bk, bv);
    attn_split_kernel<<<dim3(NQT, BH, 2), 128, ATT_SMEM>>>(mask, abias, beta, bbias);
    attn_merge_kernel<<<NSLOT, 128>>>();
    oproj_gemm_pipe_kernel<<<dim3(6, 32), 256, GEMM_SMEM>>>(bo, out);
}

// round 16
// speedup vs baseline: 1.1556x; 1.0132x over previous
#include <cuda_runtime.h>
#include <cuda_fp16.h>
#include <stdint.h>
#include <math.h>

#define BSZ 2
#define SEQ 2048
#define EMB 768
#define NH  12
#define HD  64
#define BH  (BSZ*NH)     /* 24  */
#define MTOK (BSZ*SEQ)   /* 4096 */

// ---------------------------------------------------------------------------
// Scratch (fp16 operands everywhere; V stored pair-interleaved for PV frags)
// ---------------------------------------------------------------------------
__device__ __half g_Q[BH * SEQ * HD];
__device__ __half g_K[BH * SEQ * HD];
__device__ __half g_Vp[BH * (SEQ/2) * (2*HD)];   // [bh][s/2][2d+(s&1)]
__device__ __half g_O[MTOK * EMB];               // attention out
__device__ __half g_X[MTOK * EMB];               // fp16 hidden states
__device__ __half g_W4[4 * EMB * EMB];           // fp16 Wq,Wk,Wv,Wo
__device__ int    g_mask_nz;

// ---------------------------------------------------------------------------
// Mask scan
// ---------------------------------------------------------------------------
__global__ void reset_flag_kernel() { g_mask_nz = 0; }

__global__ void scan_mask_kernel(const float* __restrict__ mask, int n4) {
    int i = blockIdx.x * blockDim.x + threadIdx.x;
    int stride = gridDim.x * blockDim.x;
    int nz = 0;
    for (; i < n4; i += stride) {
        float4 v = ((const float4*)mask)[i];
        nz |= (v.x != 0.f) | (v.y != 0.f) | (v.z != 0.f) | (v.w != 0.f);
    }
    if (__syncthreads_or(nz)) {
        if (threadIdx.x == 0) atomicOr(&g_mask_nz, 1);
    }
}

// ---------------------------------------------------------------------------
// helpers
// ---------------------------------------------------------------------------
__device__ __forceinline__ unsigned pack_h2(float lo, float hi) {
    unsigned r;
    asm("cvt.rn.f16x2.f32 %0, %2, %1;" : "=r"(r) : "f"(lo), "f"(hi));
    return r;
}

__device__ __forceinline__ void mma_f16(float c[4], const unsigned a[4],
                                        unsigned b0, unsigned b1) {
    asm("mma.sync.aligned.m16n8k16.row.col.f32.f16.f16.f32 "
        "{%0,%1,%2,%3},{%4,%5,%6,%7},{%8,%9},{%0,%1,%2,%3};"
        : "+f"(c[0]), "+f"(c[1]), "+f"(c[2]), "+f"(c[3])
        : "r"(a[0]), "r"(a[1]), "r"(a[2]), "r"(a[3]), "r"(b0), "r"(b1));
}

__device__ __forceinline__ void cp_async16(unsigned saddr, const void* gptr) {
    asm volatile("cp.async.cg.shared.global [%0], [%1], 16;"
                 :: "r"(saddr), "l"(gptr));
}
__device__ __forceinline__ void cp_commit() {
    asm volatile("cp.async.commit_group;");
}
template <int N>
__device__ __forceinline__ void cp_wait() {
    asm volatile("cp.async.wait_group %0;" :: "n"(N));
}

// ---------------------------------------------------------------------------
// Pre-round pass: X and the 4 weight matrices -> fp16.
// ---------------------------------------------------------------------------
__global__ void round_inputs_kernel(
    const float* __restrict__ X,
    const float* __restrict__ Wq, const float* __restrict__ Wk,
    const float* __restrict__ Wv, const float* __restrict__ Wo)
{
    int i = blockIdx.x * blockDim.x + threadIdx.x;
    int stride = gridDim.x * blockDim.x;
    const int NX = MTOK * EMB / 4;
    const int NW = EMB * EMB / 4;
    for (int k = i; k < NX; k += stride) {
        float4 v = ((const float4*)X)[k];
        uint2 p;
        p.x = pack_h2(v.x, v.y);
        p.y = pack_h2(v.z, v.w);
        ((uint2*)g_X)[k] = p;
    }
    const float* Ws[4] = {Wq, Wk, Wv, Wo};
#pragma unroll
    for (int s = 0; s < 4; s++) {
        uint2* dst = (uint2*)(g_W4 + (size_t)s * EMB * EMB);
        const float4* src = (const float4*)Ws[s];
        for (int k = i; k < NW; k += stride) {
            float4 v = src[k];
            uint2 p;
            p.x = pack_h2(v.x, v.y);
            p.y = pack_h2(v.z, v.w);
            dst[k] = p;
        }
    }
}

// ---------------------------------------------------------------------------
// fp16 pipelined GEMM core: C(128x128) = A(128xEMB) @ W^T(128xEMB).
// BK=64 halfs/iter (12 iters), 3-stage cp.async, one sync/iter.
// 256 thr = 8 warps (4m x 2n), warp tile 32x64, mma m16n8k16.
// smem rows: 64 data halfs, stride 72 halfs (36 half2) -> frag bank
// (4g+m+8t)%32 conflict-free for A and B.
// ---------------------------------------------------------------------------
#define DSWH 72                   /* halfs per smem row */
#define GSTH (128 * DSWH)         /* halfs per operand per stage */
#define NSTG 3
#define GEMM_SMEM (NSTG * 2 * GSTH * 2)   /* 110592 bytes */

struct GemmAcc { float a[2][8][4]; };

__device__ __forceinline__ void gemm_pipe_core_h(
    const __half* __restrict__ A, const __half* __restrict__ W,
    int bm, int bn, GemmAcc& acc, __half* sm)
{
    int tid = threadIdx.x;
    int lane = tid & 31;
    int wid = tid >> 5;
    int g = lane >> 2, m = lane & 3;
    int wm = wid & 3, wn = wid >> 2;

#pragma unroll
    for (int im = 0; im < 2; im++)
#pragma unroll
        for (int jn = 0; jn < 8; jn++)
#pragma unroll
            for (int i = 0; i < 4; i++) acc.a[im][jn][i] = 0.f;

    unsigned sbase = (unsigned)__cvta_generic_to_shared(sm);
    int rowc = tid >> 1;                 // 0..127
    int hof  = (tid & 1) * 32;           // half offset within row chunk
    const __half* agp = A + (size_t)(bm + rowc) * EMB + hof;
    const __half* bgp = W + (size_t)(bn + rowc) * EMB + hof;
    unsigned soff = (unsigned)(rowc * DSWH + hof) * 2;

    auto issue = [&](int it) {
        int st = it % NSTG;
        unsigned as_ = sbase + (unsigned)st * (2 * GSTH * 2);
        unsigned bs_ = as_ + GSTH * 2;
        int k0 = it * 64;
#pragma unroll
        for (int u = 0; u < 4; u++) {
            cp_async16(as_ + soff + u * 16, agp + k0 + u * 8);
            cp_async16(bs_ + soff + u * 16, bgp + k0 + u * 8);
        }
        cp_commit();
    };

    const int NIT = EMB / 64;   // 12
    issue(0);
    issue(1);

    for (int it = 0; it < NIT; it++) {
        if (it + 1 < NIT) cp_wait<1>();
        else              cp_wait<0>();
        __syncthreads();
        if (it + 2 < NIT) issue(it + 2);

        const unsigned* Au = (const unsigned*)(sm + (it % NSTG) * 2 * GSTH);
        const unsigned* Bu = Au + GSTH / 2;

#pragma unroll
        for (int t = 0; t < 4; t++) {
            unsigned af[2][4];
#pragma unroll
            for (int im = 0; im < 2; im++) {
                const unsigned* ar = Au + (wm * 32 + im * 16 + g) * 36 + 8 * t + m;
                af[im][0] = ar[0];
                af[im][1] = ar[8 * 36];
                af[im][2] = ar[4];
                af[im][3] = ar[8 * 36 + 4];
            }
#pragma unroll
            for (int jn = 0; jn < 8; jn++) {
                const unsigned* br = Bu + (wn * 64 + jn * 8 + g) * 36 + 8 * t + m;
                unsigned b0 = br[0];
                unsigned b1 = br[4];
                mma_f16(acc.a[0][jn], af[0], b0, b1);
                mma_f16(acc.a[1][jn], af[1], b0, b1);
            }
        }
    }
}

// ---------------------------------------------------------------------------
// QKV projection: grid (18, 32). Q/K -> fp16 [bh][s][d]; V -> g_Vp interleaved.
// ---------------------------------------------------------------------------
__global__ void __launch_bounds__(256) qkv_gemm_pipe_kernel(
    const float* __restrict__ bq, const float* __restrict__ bk,
    const float* __restrict__ bv)
{
    extern __shared__ __align__(16) __half smh[];

    int bx  = blockIdx.x;
    int seg = bx / 6;
    int nb  = bx % 6;
    int bm  = blockIdx.y * 128;

    const __half* W   = g_W4 + (size_t)seg * EMB * EMB;
    const float* bias = (seg == 0) ? bq : (seg == 1) ? bk : bv;
    const float scale = (seg == 0) ? 0.125f : 1.0f;

    GemmAcc acc;
    gemm_pipe_core_h(g_X, W, bm, nb * 128, acc, smh);

    int lane = threadIdx.x & 31;
    int wid  = threadIdx.x >> 5;
    int g = lane >> 2, m = lane & 3;
    int wm = wid & 3, wn = wid >> 2;

#pragma unroll
    for (int im = 0; im < 2; im++) {
        int r0 = bm + wm * 32 + im * 16 + g;
        int b = r0 >> 11, s0 = r0 & 2047;
#pragma unroll
        for (int jn = 0; jn < 8; jn++) {
            int nloc = nb * 128 + wn * 64 + jn * 8 + 2 * m;
            int h = nloc >> 6, d = nloc & 63;
            float b0v = bias[nloc], b1v = bias[nloc + 1];
            int bh = b * NH + h;
            float v0x = (acc.a[im][jn][0] + b0v) * scale;
            float v0y = (acc.a[im][jn][1] + b1v) * scale;
            float v1x = (acc.a[im][jn][2] + b0v) * scale;
            float v1y = (acc.a[im][jn][3] + b1v) * scale;
            if (seg < 2) {
                __half* out = (seg == 0) ? g_Q : g_K;
                __half* o0 = out + ((size_t)bh * SEQ + s0) * HD + d;
                *(unsigned*)o0            = pack_h2(v0x, v0y);
                *(unsigned*)(o0 + 8 * HD) = pack_h2(v1x, v1y);
            } else {
                // V: pair-interleave rows into g_Vp[bh][s/2][2d + (s&1)]
                int sp0 = s0 >> 1, par = s0 & 1;
                __half* p0 = g_Vp + ((size_t)bh * (SEQ/2) + sp0) * (2*HD);
                __half* p1 = p0 + 4 * (2*HD);   // row s0+8 -> sp0+4
                p0[2*d + par]     = __float2half_rn(v0x);
                p0[2*(d+1) + par] = __float2half_rn(v0y);
                p1[2*d + par]     = __float2half_rn(v1x);
                p1[2*(d+1) + par] = __float2half_rn(v1y);
            }
        }
    }
}

// ---------------------------------------------------------------------------
// Output projection: grid (6, 32). d_out = g_O @ Wo^T + bo (fp32 out).
// ---------------------------------------------------------------------------
__global__ void __launch_bounds__(256) oproj_gemm_pipe_kernel(
    const float* __restrict__ bias, float* __restrict__ C)
{
    extern __shared__ __align__(16) __half smh[];

    int bn = blockIdx.x * 128;
    int bm = blockIdx.y * 128;

    GemmAcc acc;
    gemm_pipe_core_h(g_O, g_W4 + (size_t)3 * EMB * EMB, bm, bn, acc, smh);

    int lane = threadIdx.x & 31;
    int wid  = threadIdx.x >> 5;
    int g = lane >> 2, m = lane & 3;
    int wm = wid & 3, wn = wid >> 2;

#pragma unroll
    for (int im = 0; im < 2; im++) {
        int r0 = bm + wm * 32 + im * 16 + g;
#pragma unroll
        for (int jn = 0; jn < 8; jn++) {
            int n = bn + wn * 64 + jn * 8 + 2 * m;
            float b0v = bias[n], b1v = bias[n + 1];
            float* o0 = C + (size_t)r0 * EMB + n;
            float* o1 = o0 + (size_t)8 * EMB;
            *(float2*)o0 = make_float2(acc.a[im][jn][0] + b0v, acc.a[im][jn][1] + b1v);
            *(float2*)o1 = make_float2(acc.a[im][jn][2] + b0v, acc.a[im][jn][3] + b1v);
        }
    }
}

// ---------------------------------------------------------------------------
// Flash attention v6: fp16 m16n8k16, single-pass (R9 structure), 128 thr.
// Per warp: 32 q-rows (im=2). 64-key tiles, double-buffered cp.async.
// Scores: 4 k16-steps x 8 key-blocks. PV: P C-frags pack directly into
// A-frags (f16x2); V read from pair-interleaved smem -> single LDS.32 frags.
// Smem rows: K stride 72 halfs (bank 4g+m+8t), Vp stride 144 halfs
// (bank 8m+g+8d) -> conflict-free.
// ---------------------------------------------------------------------------
#define KPADH 72                       /* K smem row halfs  */
#define VPADH 144                      /* Vp smem row halfs */
#define ATT_STAGE (64*KPADH*2 + 32*VPADH*2)   /* 18432 B */
#define ATT_SMEM  (2 * ATT_STAGE)              /* 36864 B */

__global__ void __launch_bounds__(128) attn_f16_kernel(
    const float* __restrict__ mask,
    const float* __restrict__ attn_bias,
    const float* __restrict__ beta_p,
    const float* __restrict__ bbias_p)
{
    extern __shared__ __align__(16) __half smh[];

    int qt   = blockIdx.x;
    int bh   = blockIdx.y;
    int b    = bh / NH;
    int h    = bh % NH;
    int q0   = qt * 128;
    int tid  = threadIdx.x;
    int w    = tid >> 5;
    int lane = tid & 31;
    int g    = lane >> 2;
    int m    = lane & 3;

    const float beta  = beta_p[0];
    const float bbias = bbias_p[0];
    const int masknz  = g_mask_nz;

    const __half* Kg  = g_K + (size_t)bh * SEQ * HD;
    const __half* Vpg = g_Vp + (size_t)bh * (SEQ/2) * (2*HD);
    const float* biasg = attn_bias + (size_t)bh * SEQ;

    // Q fragments: fp16, 4 k16-steps
    unsigned qf[2][4][4];
    {
        const __half* Qb = g_Q + ((size_t)bh * SEQ + q0 + w * 32) * HD;
#pragma unroll
        for (int im = 0; im < 2; im++) {
            const unsigned* r0 = (const unsigned*)(Qb + (size_t)(im * 16 + g) * HD);
            const unsigned* r1 = (const unsigned*)(Qb + (size_t)(im * 16 + g + 8) * HD);
#pragma unroll
            for (int t = 0; t < 4; t++) {
                qf[im][t][0] = r0[8 * t + m];
                qf[im][t][1] = r1[8 * t + m];
                qf[im][t][2] = r0[8 * t + m + 4];
                qf[im][t][3] = r1[8 * t + m + 4];
            }
        }
    }

    float mr[2][2], lrn[2][2];
    float oa[2][8][4];
#pragma unroll
    for (int im = 0; im < 2; im++) {
        mr[im][0] = -1e30f; mr[im][1] = -1e30f;
        lrn[im][0] = 0.f;   lrn[im][1] = 0.f;
#pragma unroll
        for (int d = 0; d < 8; d++)
#pragma unroll
            for (int i = 0; i < 4; i++) oa[im][d][i] = 0.f;
    }

    unsigned sbase = (unsigned)__cvta_generic_to_shared(smh);

    auto issue_tile = [&](int kt) {
        unsigned kst = sbase + (unsigned)(kt & 1) * ATT_STAGE;
        unsigned vst = kst + 64 * KPADH * 2;
        // K: 64 rows x 128B; 2 threads/row, 64B each
        {
            int row = tid >> 1;
            const __half* kp = Kg + (size_t)(kt * 64 + row) * HD + (tid & 1) * 32;
            unsigned so = (unsigned)(row * KPADH * 2 + (tid & 1) * 64);
#pragma unroll
            for (int u = 0; u < 4; u++)
                cp_async16(kst + so + u * 16, kp + u * 8);
        }
        // Vp: 32 rows x 256B; 4 threads/row, 64B each
        {
            int row = tid >> 2;
            const __half* vp = Vpg + (size_t)(kt * 32 + row) * (2*HD) + (tid & 3) * 32;
            unsigned so = (unsigned)(row * VPADH * 2 + (tid & 3) * 64);
#pragma unroll
            for (int u = 0; u < 4; u++)
                cp_async16(vst + so + u * 16, vp + u * 8);
        }
        cp_commit();
    };

    issue_tile(0);

    const int NT = SEQ / 64;
    for (int kt = 0; kt < NT; kt++) {
        if (kt + 1 < NT) { issue_tile(kt + 1); cp_wait<1>(); }
        else             { cp_wait<0>(); }
        __syncthreads();

        const unsigned* Ku = (const unsigned*)(smh + (kt & 1) * (ATT_STAGE/2));
        const unsigned* Vu = Ku + (64 * KPADH) / 2;
        int k0 = kt * 64;

        // ---- Scores: 4 k16-steps x 8 key blocks ----
        float sc[2][8][4];
#pragma unroll
        for (int im = 0; im < 2; im++)
#pragma unroll
            for (int j = 0; j < 8; j++)
#pragma unroll
                for (int i = 0; i < 4; i++) sc[im][j][i] = 0.f;

#pragma unroll
        for (int t = 0; t < 4; t++) {
#pragma unroll
            for (int j = 0; j < 8; j++) {
                const unsigned* kr = Ku + (8 * j + g) * 36 + 8 * t + m;
                unsigned b0 = kr[0];
                unsigned b1 = kr[4];
                mma_f16(sc[0][j], qf[0][t], b0, b1);
                mma_f16(sc[1][j], qf[1][t], b0, b1);
            }
        }

        // ---- bias (+mask) ----
#pragma unroll
        for (int j = 0; j < 8; j++) {
            float2 bv = *(const float2*)(biasg + k0 + 8 * j + 2 * m);
            float b0v = beta * bv.x + bbias;
            float b1v = beta * bv.y + bbias;
#pragma unroll
            for (int im = 0; im < 2; im++) {
                sc[im][j][0] += b0v; sc[im][j][1] += b1v;
                sc[im][j][2] += b0v; sc[im][j][3] += b1v;
                if (masknz) {
                    int qr = q0 + w * 32 + im * 16 + g;
                    const float* m0p = mask + ((size_t)b * SEQ + qr) * SEQ + k0 + 8 * j + 2 * m;
                    const float* m1p = m0p + (size_t)8 * SEQ;
                    sc[im][j][0] += m0p[0]; sc[im][j][1] += m0p[1];
                    sc[im][j][2] += m1p[0]; sc[im][j][3] += m1p[1];
                }
            }
        }

        // ---- Online softmax ----
#pragma unroll
        for (int im = 0; im < 2; im++) {
            float mx0 = sc[im][0][0], mx1 = sc[im][0][2];
#pragma unroll
            for (int j = 0; j < 8; j++) {
                mx0 = fmaxf(mx0, fmaxf(sc[im][j][0], sc[im][j][1]));
                mx1 = fmaxf(mx1, fmaxf(sc[im][j][2], sc[im][j][3]));
            }
            mx0 = fmaxf(mx0, __shfl_xor_sync(0xffffffffu, mx0, 1));
            mx0 = fmaxf(mx0, __shfl_xor_sync(0xffffffffu, mx0, 2));
            mx1 = fmaxf(mx1, __shfl_xor_sync(0xffffffffu, mx1, 1));
            mx1 = fmaxf(mx1, __shfl_xor_sync(0xffffffffu, mx1, 2));

            float mn0 = fmaxf(mr[im][0], mx0);
            float mn1 = fmaxf(mr[im][1], mx1);
            float al0 = __expf(mr[im][0] - mn0);
            float al1 = __expf(mr[im][1] - mn1);

            float s0 = 0.f, s1 = 0.f;
#pragma unroll
            for (int j = 0; j < 8; j++) {
                sc[im][j][0] = __expf(sc[im][j][0] - mn0);
                sc[im][j][1] = __expf(sc[im][j][1] - mn0);
                sc[im][j][2] = __expf(sc[im][j][2] - mn1);
                sc[im][j][3] = __expf(sc[im][j][3] - mn1);
                s0 += sc[im][j][0] + sc[im][j][1];
                s1 += sc[im][j][2] + sc[im][j][3];
            }
            s0 += __shfl_xor_sync(0xffffffffu, s0, 1);
            s0 += __shfl_xor_sync(0xffffffffu, s0, 2);
            s1 += __shfl_xor_sync(0xffffffffu, s1, 1);
            s1 += __shfl_xor_sync(0xffffffffu, s1, 2);

            lrn[im][0] = lrn[im][0] * al0 + s0;
            lrn[im][1] = lrn[im][1] * al1 + s1;
            mr[im][0] = mn0; mr[im][1] = mn1;
#pragma unroll
            for (int d = 0; d < 8; d++) {
                oa[im][d][0] *= al0; oa[im][d][1] *= al0;
                oa[im][d][2] *= al1; oa[im][d][3] *= al1;
            }
        }

        // ---- PV: C-frags pack directly into f16 A-frags; V frags are
        //      single LDS.32 from pair-interleaved smem ----
#pragma unroll
        for (int J = 0; J < 4; J++) {
            unsigned pa[2][4];
#pragma unroll
            for (int im = 0; im < 2; im++) {
                pa[im][0] = pack_h2(sc[im][2*J][0],   sc[im][2*J][1]);
                pa[im][1] = pack_h2(sc[im][2*J][2],   sc[im][2*J][3]);
                pa[im][2] = pack_h2(sc[im][2*J+1][0], sc[im][2*J+1][1]);
                pa[im][3] = pack_h2(sc[im][2*J+1][2], sc[im][2*J+1][3]);
            }
            const unsigned* vr = Vu + (8 * J + m) * 72 + g;
#pragma unroll
            for (int d = 0; d < 8; d++) {
                unsigned b0 = vr[8 * d];
                unsigned b1 = vr[4 * 72 + 8 * d];
                mma_f16(oa[0][d], pa[0], b0, b1);
                mma_f16(oa[1][d], pa[1], b0, b1);
            }
        }
        __syncthreads();
    }

    // ---- Epilogue: fp16 O ----
#pragma unroll
    for (int im = 0; im < 2; im++) {
        float inv0 = 1.f / lrn[im][0];
        float inv1 = 1.f / lrn[im][1];
        int qr = q0 + w * 32 + im * 16 + g;
        __half* O0 = g_O + ((size_t)(b * SEQ + qr)) * EMB + h * HD;
        __half* O1 = O0 + (size_t)8 * EMB;
#pragma unroll
        for (int d = 0; d < 8; d++) {
            int c = 8 * d + 2 * m;
            *(unsigned*)(O0 + c) = pack_h2(oa[im][d][0] * inv0, oa[im][d][1] * inv0);
            *(unsigned*)(O1 + c) = pack_h2(oa[im][d][2] * inv1, oa[im][d][3] * inv1);
        }
    }
}

// ---------------------------------------------------------------------------
// Launch
// ---------------------------------------------------------------------------
extern "C" void kernel_launch(void* const* d_in, const int* in_sizes, int n_in,
                              void* d_out, int out_size) {
    const float* X     = (const float*)d_in[0];
    const float* mask  = (const float*)d_in[1];
    const float* abias = (const float*)d_in[2];
    const float* Wq    = (const float*)d_in[3];
    const float* bq    = (const float*)d_in[4];
    const float* Wk    = (const float*)d_in[5];
    const float* bk    = (const float*)d_in[6];
    const float* Wv    = (const float*)d_in[7];
    const float* bv    = (const float*)d_in[8];
    const float* Wo    = (const float*)d_in[9];
    const float* bo    = (const float*)d_in[10];
    const float* beta  = (const float*)d_in[11];
    const float* bbias = (const float*)d_in[12];
    float* out = (float*)d_out;

    cudaFuncSetAttribute(attn_f16_kernel,
                         cudaFuncAttributeMaxDynamicSharedMemorySize, ATT_SMEM);
    cudaFuncSetAttribute(qkv_gemm_pipe_kernel,
                         cudaFuncAttributeMaxDynamicSharedMemorySize, GEMM_SMEM);
    cudaFuncSetAttribute(oproj_gemm_pipe_kernel,
                         cudaFuncAttributeMaxDynamicSharedMemorySize, GEMM_SMEM);

    reset_flag_kernel<<<1, 32>>>();
    scan_mask_kernel<<<1024, 256>>>(mask, BSZ * SEQ * SEQ / 4);
    round_inputs_kernel<<<512, 256>>>(X, Wq, Wk, Wv, Wo);
    qkv_gemm_pipe_kernel<<<dim3(18, 32), 256, GEMM_SMEM>>>(bq, bk, bv);
    attn_f16_kernel<<<dim3(SEQ / 128, BH), 128, ATT_SMEM>>>(mask, abias, beta, bbias);
    oproj_gemm_pipe_kernel<<<dim3(6, 32), 256, GEMM_SMEM>>>(bo, out);
}

// round 17
// speedup vs baseline: 1.7483x; 1.5129x over previous
#include <cuda_runtime.h>
#include <cuda_fp16.h>
#include <stdint.h>
#include <math.h>

#define BSZ 2
#define SEQ 2048
#define EMB 768
#define NH  12
#define HD  64
#define BH  (BSZ*NH)     /* 24  */
#define MTOK (BSZ*SEQ)   /* 4096 */

// ---------------------------------------------------------------------------
// Scratch (fp16 operands everywhere; V stored pair-interleaved for PV frags)
// ---------------------------------------------------------------------------
__device__ __half g_Q[BH * SEQ * HD];
__device__ __half g_K[BH * SEQ * HD];
__device__ __half g_Vp[BH * (SEQ/2) * (2*HD)];   // [bh][s/2][2d+(s&1)]
__device__ __half g_O[MTOK * EMB];               // attention out
__device__ __half g_X[MTOK * EMB];               // fp16 hidden states
__device__ __half g_W4[4 * EMB * EMB];           // fp16 Wq,Wk,Wv,Wo
__device__ int    g_mask_nz;

// ---------------------------------------------------------------------------
// Mask scan
// ---------------------------------------------------------------------------
__global__ void reset_flag_kernel() { g_mask_nz = 0; }

__global__ void scan_mask_kernel(const float* __restrict__ mask, int n4) {
    int i = blockIdx.x * blockDim.x + threadIdx.x;
    int stride = gridDim.x * blockDim.x;
    int nz = 0;
    for (; i < n4; i += stride) {
        float4 v = ((const float4*)mask)[i];
        nz |= (v.x != 0.f) | (v.y != 0.f) | (v.z != 0.f) | (v.w != 0.f);
    }
    if (__syncthreads_or(nz)) {
        if (threadIdx.x == 0) atomicOr(&g_mask_nz, 1);
    }
}

// ---------------------------------------------------------------------------
// helpers
// ---------------------------------------------------------------------------
__device__ __forceinline__ unsigned pack_h2(float lo, float hi) {
    unsigned r;
    asm("cvt.rn.f16x2.f32 %0, %2, %1;" : "=r"(r) : "f"(lo), "f"(hi));
    return r;
}

__device__ __forceinline__ void mma_f16(float c[4], const unsigned a[4],
                                        unsigned b0, unsigned b1) {
    asm("mma.sync.aligned.m16n8k16.row.col.f32.f16.f16.f32 "
        "{%0,%1,%2,%3},{%4,%5,%6,%7},{%8,%9},{%0,%1,%2,%3};"
        : "+f"(c[0]), "+f"(c[1]), "+f"(c[2]), "+f"(c[3])
        : "r"(a[0]), "r"(a[1]), "r"(a[2]), "r"(a[3]), "r"(b0), "r"(b1));
}

__device__ __forceinline__ void cp_async16(unsigned saddr, const void* gptr) {
    asm volatile("cp.async.cg.shared.global [%0], [%1], 16;"
                 :: "r"(saddr), "l"(gptr));
}
__device__ __forceinline__ void cp_commit() {
    asm volatile("cp.async.commit_group;");
}
template <int N>
__device__ __forceinline__ void cp_wait() {
    asm volatile("cp.async.wait_group %0;" :: "n"(N));
}

// ---------------------------------------------------------------------------
// Pre-round pass: X and the 4 weight matrices -> fp16.
// ---------------------------------------------------------------------------
__global__ void round_inputs_kernel(
    const float* __restrict__ X,
    const float* __restrict__ Wq, const float* __restrict__ Wk,
    const float* __restrict__ Wv, const float* __restrict__ Wo)
{
    int i = blockIdx.x * blockDim.x + threadIdx.x;
    int stride = gridDim.x * blockDim.x;
    const int NX = MTOK * EMB / 4;
    const int NW = EMB * EMB / 4;
    for (int k = i; k < NX; k += stride) {
        float4 v = ((const float4*)X)[k];
        uint2 p;
        p.x = pack_h2(v.x, v.y);
        p.y = pack_h2(v.z, v.w);
        ((uint2*)g_X)[k] = p;
    }
    const float* Ws[4] = {Wq, Wk, Wv, Wo};
#pragma unroll
    for (int s = 0; s < 4; s++) {
        uint2* dst = (uint2*)(g_W4 + (size_t)s * EMB * EMB);
        const float4* src = (const float4*)Ws[s];
        for (int k = i; k < NW; k += stride) {
            float4 v = src[k];
            uint2 p;
            p.x = pack_h2(v.x, v.y);
            p.y = pack_h2(v.z, v.w);
            dst[k] = p;
        }
    }
}

// ---------------------------------------------------------------------------
// fp16 pipelined GEMM core (qkv): C(128x128) = A(128xEMB) @ W^T(128xEMB).
// BK=64 halfs/iter (12 iters), 3-stage cp.async, one sync/iter. 256 thr,
// warp tile 32x64, mma m16n8k16. Proven 122us.
// ---------------------------------------------------------------------------
#define DSWH 72                   /* halfs per smem row */
#define GSTH (128 * DSWH)         /* halfs per operand per stage */
#define NSTG 3
#define GEMM_SMEM (NSTG * 2 * GSTH * 2)   /* 110592 bytes */

struct GemmAcc { float a[2][8][4]; };

__device__ __forceinline__ void gemm_pipe_core_h(
    const __half* __restrict__ A, const __half* __restrict__ W,
    int bm, int bn, GemmAcc& acc, __half* sm)
{
    int tid = threadIdx.x;
    int lane = tid & 31;
    int wid = tid >> 5;
    int g = lane >> 2, m = lane & 3;
    int wm = wid & 3, wn = wid >> 2;

#pragma unroll
    for (int im = 0; im < 2; im++)
#pragma unroll
        for (int jn = 0; jn < 8; jn++)
#pragma unroll
            for (int i = 0; i < 4; i++) acc.a[im][jn][i] = 0.f;

    unsigned sbase = (unsigned)__cvta_generic_to_shared(sm);
    int rowc = tid >> 1;
    int hof  = (tid & 1) * 32;
    const __half* agp = A + (size_t)(bm + rowc) * EMB + hof;
    const __half* bgp = W + (size_t)(bn + rowc) * EMB + hof;
    unsigned soff = (unsigned)(rowc * DSWH + hof) * 2;

    auto issue = [&](int it) {
        int st = it % NSTG;
        unsigned as_ = sbase + (unsigned)st * (2 * GSTH * 2);
        unsigned bs_ = as_ + GSTH * 2;
        int k0 = it * 64;
#pragma unroll
        for (int u = 0; u < 4; u++) {
            cp_async16(as_ + soff + u * 16, agp + k0 + u * 8);
            cp_async16(bs_ + soff + u * 16, bgp + k0 + u * 8);
        }
        cp_commit();
    };

    const int NIT = EMB / 64;   // 12
    issue(0);
    issue(1);

    for (int it = 0; it < NIT; it++) {
        if (it + 1 < NIT) cp_wait<1>();
        else              cp_wait<0>();
        __syncthreads();
        if (it + 2 < NIT) issue(it + 2);

        const unsigned* Au = (const unsigned*)(sm + (it % NSTG) * 2 * GSTH);
        const unsigned* Bu = Au + GSTH / 2;

#pragma unroll
        for (int t = 0; t < 4; t++) {
            unsigned af[2][4];
#pragma unroll
            for (int im = 0; im < 2; im++) {
                const unsigned* ar = Au + (wm * 32 + im * 16 + g) * 36 + 8 * t + m;
                af[im][0] = ar[0];
                af[im][1] = ar[8 * 36];
                af[im][2] = ar[4];
                af[im][3] = ar[8 * 36 + 4];
            }
#pragma unroll
            for (int jn = 0; jn < 8; jn++) {
                const unsigned* br = Bu + (wn * 64 + jn * 8 + g) * 36 + 8 * t + m;
                unsigned b0 = br[0];
                unsigned b1 = br[4];
                mma_f16(acc.a[0][jn], af[0], b0, b1);
                mma_f16(acc.a[1][jn], af[1], b0, b1);
            }
        }
    }
}

// ---------------------------------------------------------------------------
// QKV projection: grid (18, 32). Q/K -> fp16 [bh][s][d]; V -> g_Vp interleaved.
// ---------------------------------------------------------------------------
__global__ void __launch_bounds__(256) qkv_gemm_pipe_kernel(
    const float* __restrict__ bq, const float* __restrict__ bk,
    const float* __restrict__ bv)
{
    extern __shared__ __align__(16) __half smh[];

    int bx  = blockIdx.x;
    int seg = bx / 6;
    int nb  = bx % 6;
    int bm  = blockIdx.y * 128;

    const __half* W   = g_W4 + (size_t)seg * EMB * EMB;
    const float* bias = (seg == 0) ? bq : (seg == 1) ? bk : bv;
    const float scale = (seg == 0) ? 0.125f : 1.0f;

    GemmAcc acc;
    gemm_pipe_core_h(g_X, W, bm, nb * 128, acc, smh);

    int lane = threadIdx.x & 31;
    int wid  = threadIdx.x >> 5;
    int g = lane >> 2, m = lane & 3;
    int wm = wid & 3, wn = wid >> 2;

#pragma unroll
    for (int im = 0; im < 2; im++) {
        int r0 = bm + wm * 32 + im * 16 + g;
        int b = r0 >> 11, s0 = r0 & 2047;
#pragma unroll
        for (int jn = 0; jn < 8; jn++) {
            int nloc = nb * 128 + wn * 64 + jn * 8 + 2 * m;
            int h = nloc >> 6, d = nloc & 63;
            float b0v = bias[nloc], b1v = bias[nloc + 1];
            int bh = b * NH + h;
            float v0x = (acc.a[im][jn][0] + b0v) * scale;
            float v0y = (acc.a[im][jn][1] + b1v) * scale;
            float v1x = (acc.a[im][jn][2] + b0v) * scale;
            float v1y = (acc.a[im][jn][3] + b1v) * scale;
            if (seg < 2) {
                __half* out = (seg == 0) ? g_Q : g_K;
                __half* o0 = out + ((size_t)bh * SEQ + s0) * HD + d;
                *(unsigned*)o0            = pack_h2(v0x, v0y);
                *(unsigned*)(o0 + 8 * HD) = pack_h2(v1x, v1y);
            } else {
                int sp0 = s0 >> 1, par = s0 & 1;
                __half* p0 = g_Vp + ((size_t)bh * (SEQ/2) + sp0) * (2*HD);
                __half* p1 = p0 + 4 * (2*HD);
                p0[2*d + par]     = __float2half_rn(v0x);
                p0[2*(d+1) + par] = __float2half_rn(v0y);
                p1[2*d + par]     = __float2half_rn(v1x);
                p1[2*(d+1) + par] = __float2half_rn(v1y);
            }
        }
    }
}

// ---------------------------------------------------------------------------
// oproj fp16 core, BM=64 x BN=128 tiles, 2-stage, 55KB smem -> 4 CTAs/SM.
// 256 thr = 8 warps (2m x 4n), warp tile 32x32 (im=2, jn<4).
// Grid (6, 64) = 384 CTAs <= 592 slots -> one wave of half-size CTAs.
// ---------------------------------------------------------------------------
#define O_AST (64 * DSWH)            /* A halfs per stage */
#define O_BST (128 * DSWH)           /* B halfs per stage */
#define O_STG (O_AST + O_BST)
#define OPROJ_SMEM (2 * O_STG * 2)   /* 55296 bytes */

__global__ void __launch_bounds__(256) oproj_gemm64_kernel(
    const float* __restrict__ bias, float* __restrict__ C)
{
    extern __shared__ __align__(16) __half smh[];

    int bn = blockIdx.x * 128;
    int bm = blockIdx.y * 64;

    int tid = threadIdx.x;
    int lane = tid & 31;
    int wid = tid >> 5;
    int g = lane >> 2, m = lane & 3;
    int wm = wid & 1, wn = wid >> 1;

    float acc[2][4][4];
#pragma unroll
    for (int im = 0; im < 2; im++)
#pragma unroll
        for (int jn = 0; jn < 4; jn++)
#pragma unroll
            for (int i = 0; i < 4; i++) acc[im][jn][i] = 0.f;

    unsigned sbase = (unsigned)__cvta_generic_to_shared(smh);
    const __half* Wo = g_W4 + (size_t)3 * EMB * EMB;

    // A loader: 64 rows, 4 threads/row, 2 chunks each
    int rowA = tid >> 2;
    int chA  = (tid & 3) * 16;           // half offset of first chunk
    const __half* agp = g_O + (size_t)(bm + rowA) * EMB + chA;
    unsigned soffA = (unsigned)(rowA * DSWH + chA) * 2;
    // B loader: 128 rows, 2 threads/row, 4 chunks each
    int rowB = tid >> 1;
    int chB  = (tid & 1) * 32;
    const __half* bgp = Wo + (size_t)(bn + rowB) * EMB + chB;
    unsigned soffB = (unsigned)(rowB * DSWH + chB) * 2;

    auto issue = [&](int it) {
        unsigned base = sbase + (unsigned)(it & 1) * (O_STG * 2);
        unsigned bsB  = base + O_AST * 2;
        int k0 = it * 64;
        cp_async16(base + soffA,      agp + k0);
        cp_async16(base + soffA + 16, agp + k0 + 8);
#pragma unroll
        for (int u = 0; u < 4; u++)
            cp_async16(bsB + soffB + u * 16, bgp + k0 + u * 8);
        cp_commit();
    };

    const int NIT = EMB / 64;   // 12
    issue(0);

    for (int it = 0; it < NIT; it++) {
        if (it + 1 < NIT) { issue(it + 1); cp_wait<1>(); }
        else              { cp_wait<0>(); }
        __syncthreads();

        const unsigned* Au = (const unsigned*)(smh + (it & 1) * O_STG);
        const unsigned* Bu = Au + O_AST / 2;

#pragma unroll
        for (int t = 0; t < 4; t++) {
            unsigned af[2][4];
#pragma unroll
            for (int im = 0; im < 2; im++) {
                const unsigned* ar = Au + (wm * 32 + im * 16 + g) * 36 + 8 * t + m;
                af[im][0] = ar[0];
                af[im][1] = ar[8 * 36];
                af[im][2] = ar[4];
                af[im][3] = ar[8 * 36 + 4];
            }
#pragma unroll
            for (int jn = 0; jn < 4; jn++) {
                const unsigned* br = Bu + (wn * 32 + jn * 8 + g) * 36 + 8 * t + m;
                unsigned b0 = br[0];
                unsigned b1 = br[4];
                mma_f16(acc[0][jn], af[0], b0, b1);
                mma_f16(acc[1][jn], af[1], b0, b1);
            }
        }
        __syncthreads();
    }

#pragma unroll
    for (int im = 0; im < 2; im++) {
        int r0 = bm + wm * 32 + im * 16 + g;
#pragma unroll
        for (int jn = 0; jn < 4; jn++) {
            int n = bn + wn * 32 + jn * 8 + 2 * m;
            float b0v = bias[n], b1v = bias[n + 1];
            float* o0 = C + (size_t)r0 * EMB + n;
            float* o1 = o0 + (size_t)8 * EMB;
            *(float2*)o0 = make_float2(acc[im][jn][0] + b0v, acc[im][jn][1] + b1v);
            *(float2*)o1 = make_float2(acc[im][jn][2] + b0v, acc[im][jn][3] + b1v);
        }
    }
}

// ---------------------------------------------------------------------------
// Flash attention v6b: fp16 m16n8k16, 3-stage cp.async pipeline (55KB,
// 4 CTAs/SM). Inner loop identical to R16 (proven correct).
// ---------------------------------------------------------------------------
#define KPADH 72
#define VPADH 144
#define ATT_STAGE (64*KPADH*2 + 32*VPADH*2)   /* 18432 B */
#define ATT_NSTG 3
#define ATT_SMEM  (ATT_NSTG * ATT_STAGE)      /* 55296 B */

__global__ void __launch_bounds__(128) attn_f16_kernel(
    const float* __restrict__ mask,
    const float* __restrict__ attn_bias,
    const float* __restrict__ beta_p,
    const float* __restrict__ bbias_p)
{
    extern __shared__ __align__(16) __half smh[];

    int qt   = blockIdx.x;
    int bh   = blockIdx.y;
    int b    = bh / NH;
    int h    = bh % NH;
    int q0   = qt * 128;
    int tid  = threadIdx.x;
    int w    = tid >> 5;
    int lane = tid & 31;
    int g    = lane >> 2;
    int m    = lane & 3;

    const float beta  = beta_p[0];
    const float bbias = bbias_p[0];
    const int masknz  = g_mask_nz;

    const __half* Kg  = g_K + (size_t)bh * SEQ * HD;
    const __half* Vpg = g_Vp + (size_t)bh * (SEQ/2) * (2*HD);
    const float* biasg = attn_bias + (size_t)bh * SEQ;

    unsigned qf[2][4][4];
    {
        const __half* Qb = g_Q + ((size_t)bh * SEQ + q0 + w * 32) * HD;
#pragma unroll
        for (int im = 0; im < 2; im++) {
            const unsigned* r0 = (const unsigned*)(Qb + (size_t)(im * 16 + g) * HD);
            const unsigned* r1 = (const unsigned*)(Qb + (size_t)(im * 16 + g + 8) * HD);
#pragma unroll
            for (int t = 0; t < 4; t++) {
                qf[im][t][0] = r0[8 * t + m];
                qf[im][t][1] = r1[8 * t + m];
                qf[im][t][2] = r0[8 * t + m + 4];
                qf[im][t][3] = r1[8 * t + m + 4];
            }
        }
    }

    float mr[2][2], lrn[2][2];
    float oa[2][8][4];
#pragma unroll
    for (int im = 0; im < 2; im++) {
        mr[im][0] = -1e30f; mr[im][1] = -1e30f;
        lrn[im][0] = 0.f;   lrn[im][1] = 0.f;
#pragma unroll
        for (int d = 0; d < 8; d++)
#pragma unroll
            for (int i = 0; i < 4; i++) oa[im][d][i] = 0.f;
    }

    unsigned sbase = (unsigned)__cvta_generic_to_shared(smh);

    auto issue_tile = [&](int kt) {
        unsigned kst = sbase + (unsigned)(kt % ATT_NSTG) * ATT_STAGE;
        unsigned vst = kst + 64 * KPADH * 2;
        {
            int row = tid >> 1;
            const __half* kp = Kg + (size_t)(kt * 64 + row) * HD + (tid & 1) * 32;
            unsigned so = (unsigned)(row * KPADH * 2 + (tid & 1) * 64);
#pragma unroll
            for (int u = 0; u < 4; u++)
                cp_async16(kst + so + u * 16, kp + u * 8);
        }
        {
            int row = tid >> 2;
            const __half* vp = Vpg + (size_t)(kt * 32 + row) * (2*HD) + (tid & 3) * 32;
            unsigned so = (unsigned)(row * VPADH * 2 + (tid & 3) * 64);
#pragma unroll
            for (int u = 0; u < 4; u++)
                cp_async16(vst + so + u * 16, vp + u * 8);
        }
        cp_commit();
    };

    issue_tile(0);
    issue_tile(1);

    const int NT = SEQ / 64;
    for (int kt = 0; kt < NT; kt++) {
        if (kt + 2 < NT)      { issue_tile(kt + 2); cp_wait<2>(); }
        else if (kt + 1 < NT) { cp_wait<1>(); }
        else                  { cp_wait<0>(); }
        __syncthreads();

        const unsigned* Ku = (const unsigned*)(smh + (kt % ATT_NSTG) * (ATT_STAGE/2));
        const unsigned* Vu = Ku + (64 * KPADH) / 2;
        int k0 = kt * 64;

        float sc[2][8][4];
#pragma unroll
        for (int im = 0; im < 2; im++)
#pragma unroll
            for (int j = 0; j < 8; j++)
#pragma unroll
                for (int i = 0; i < 4; i++) sc[im][j][i] = 0.f;

#pragma unroll
        for (int t = 0; t < 4; t++) {
#pragma unroll
            for (int j = 0; j < 8; j++) {
                const unsigned* kr = Ku + (8 * j + g) * 36 + 8 * t + m;
                unsigned b0 = kr[0];
                unsigned b1 = kr[4];
                mma_f16(sc[0][j], qf[0][t], b0, b1);
                mma_f16(sc[1][j], qf[1][t], b0, b1);
            }
        }

#pragma unroll
        for (int j = 0; j < 8; j++) {
            float2 bv = *(const float2*)(biasg + k0 + 8 * j + 2 * m);
            float b0v = beta * bv.x + bbias;
            float b1v = beta * bv.y + bbias;
#pragma unroll
            for (int im = 0; im < 2; im++) {
                sc[im][j][0] += b0v; sc[im][j][1] += b1v;
                sc[im][j][2] += b0v; sc[im][j][3] += b1v;
                if (masknz) {
                    int qr = q0 + w * 32 + im * 16 + g;
                    const float* m0p = mask + ((size_t)b * SEQ + qr) * SEQ + k0 + 8 * j + 2 * m;
                    const float* m1p = m0p + (size_t)8 * SEQ;
                    sc[im][j][0] += m0p[0]; sc[im][j][1] += m0p[1];
                    sc[im][j][2] += m1p[0]; sc[im][j][3] += m1p[1];
                }
            }
        }

#pragma unroll
        for (int im = 0; im < 2; im++) {
            float mx0 = sc[im][0][0], mx1 = sc[im][0][2];
#pragma unroll
            for (int j = 0; j < 8; j++) {
                mx0 = fmaxf(mx0, fmaxf(sc[im][j][0], sc[im][j][1]));
                mx1 = fmaxf(mx1, fmaxf(sc[im][j][2], sc[im][j][3]));
            }
            mx0 = fmaxf(mx0, __shfl_xor_sync(0xffffffffu, mx0, 1));
            mx0 = fmaxf(mx0, __shfl_xor_sync(0xffffffffu, mx0, 2));
            mx1 = fmaxf(mx1, __shfl_xor_sync(0xffffffffu, mx1, 1));
            mx1 = fmaxf(mx1, __shfl_xor_sync(0xffffffffu, mx1, 2));

            float mn0 = fmaxf(mr[im][0], mx0);
            float mn1 = fmaxf(mr[im][1], mx1);
            float al0 = __expf(mr[im][0] - mn0);
            float al1 = __expf(mr[im][1] - mn1);

            float s0 = 0.f, s1 = 0.f;
#pragma unroll
            for (int j = 0; j < 8; j++) {
                sc[im][j][0] = __expf(sc[im][j][0] - mn0);
                sc[im][j][1] = __expf(sc[im][j][1] - mn0);
                sc[im][j][2] = __expf(sc[im][j][2] - mn1);
                sc[im][j][3] = __expf(sc[im][j][3] - mn1);
                s0 += sc[im][j][0] + sc[im][j][1];
                s1 += sc[im][j][2] + sc[im][j][3];
            }
            s0 += __shfl_xor_sync(0xffffffffu, s0, 1);
            s0 += __shfl_xor_sync(0xffffffffu, s0, 2);
            s1 += __shfl_xor_sync(0xffffffffu, s1, 1);
            s1 += __shfl_xor_sync(0xffffffffu, s1, 2);

            lrn[im][0] = lrn[im][0] * al0 + s0;
            lrn[im][1] = lrn[im][1] * al1 + s1;
            mr[im][0] = mn0; mr[im][1] = mn1;
#pragma unroll
            for (int d = 0; d < 8; d++) {
                oa[im][d][0] *= al0; oa[im][d][1] *= al0;
                oa[im][d][2] *= al1; oa[im][d][3] *= al1;
            }
        }

#pragma unroll
        for (int J = 0; J < 4; J++) {
            unsigned pa[2][4];
#pragma unroll
            for (int im = 0; im < 2; im++) {
                pa[im][0] = pack_h2(sc[im][2*J][0],   sc[im][2*J][1]);
                pa[im][1] = pack_h2(sc[im][2*J][2],   sc[im][2*J][3]);
                pa[im][2] = pack_h2(sc[im][2*J+1][0], sc[im][2*J+1][1]);
                pa[im][3] = pack_h2(sc[im][2*J+1][2], sc[im][2*J+1][3]);
            }
            const unsigned* vr = Vu + (8 * J + m) * 72 + g;
#pragma unroll
            for (int d = 0; d < 8; d++) {
                unsigned b0 = vr[8 * d];
                unsigned b1 = vr[4 * 72 + 8 * d];
                mma_f16(oa[0][d], pa[0], b0, b1);
                mma_f16(oa[1][d], pa[1], b0, b1);
            }
        }
        __syncthreads();
    }

#pragma unroll
    for (int im = 0; im < 2; im++) {
        float inv0 = 1.f / lrn[im][0];
        float inv1 = 1.f / lrn[im][1];
        int qr = q0 + w * 32 + im * 16 + g;
        __half* O0 = g_O + ((size_t)(b * SEQ + qr)) * EMB + h * HD;
        __half* O1 = O0 + (size_t)8 * EMB;
#pragma unroll
        for (int d = 0; d < 8; d++) {
            int c = 8 * d + 2 * m;
            *(unsigned*)(O0 + c) = pack_h2(oa[im][d][0] * inv0, oa[im][d][1] * inv0);
            *(unsigned*)(O1 + c) = pack_h2(oa[im][d][2] * inv1, oa[im][d][3] * inv1);
        }
    }
}

// ---------------------------------------------------------------------------
// Launch
// ---------------------------------------------------------------------------
extern "C" void kernel_launch(void* const* d_in, const int* in_sizes, int n_in,
                              void* d_out, int out_size) {
    const float* X     = (const float*)d_in[0];
    const float* mask  = (const float*)d_in[1];
    const float* abias = (const float*)d_in[2];
    const float* Wq    = (const float*)d_in[3];
    const float* bq    = (const float*)d_in[4];
    const float* Wk    = (const float*)d_in[5];
    const float* bk    = (const float*)d_in[6];
    const float* Wv    = (const float*)d_in[7];
    const float* bv    = (const float*)d_in[8];
    const float* Wo    = (const float*)d_in[9];
    const float* bo    = (const float*)d_in[10];
    const float* beta  = (const float*)d_in[11];
    const float* bbias = (const float*)d_in[12];
    float* out = (float*)d_out;

    cudaFuncSetAttribute(attn_f16_kernel,
                         cudaFuncAttributeMaxDynamicSharedMemorySize, ATT_SMEM);
    cudaFuncSetAttribute(qkv_gemm_pipe_kernel,
                         cudaFuncAttributeMaxDynamicSharedMemorySize, GEMM_SMEM);
    cudaFuncSetAttribute(oproj_gemm64_kernel,
                         cudaFuncAttributeMaxDynamicSharedMemorySize, OPROJ_SMEM);

    reset_flag_kernel<<<1, 32>>>();
    scan_mask_kernel<<<1024, 256>>>(mask, BSZ * SEQ * SEQ / 4);
    round_inputs_kernel<<<512, 256>>>(X, Wq, Wk, Wv, Wo);
    qkv_gemm_pipe_kernel<<<dim3(18, 32), 256, GEMM_SMEM>>>(bq, bk, bv);
    attn_f16_kernel<<<dim3(SEQ / 128, BH), 128, ATT_SMEM>>>(mask, abias, beta, bbias);
    oproj_gemm64_kernel<<<dim3(6, 64), 256, OPROJ_SMEM>>>(bo, out);
}